// round 4
// baseline (speedup 1.0000x reference)
#include <cuda_runtime.h>

#define W 15            // attention block length
#define DIM 64          // head dim
#define BLK_PER_CTA 4   // attention blocks per CTA (1 per warp)
#define NTHREADS 128
#define SST 964         // floats per block in smem (960 + 4 pad)
#define EPS 1e-6f

typedef unsigned long long ull;

__device__ __forceinline__ ull pack2(float lo, float hi) {
    ull r; asm("mov.b64 %0, {%1,%2};" : "=l"(r) : "f"(lo), "f"(hi)); return r;
}
__device__ __forceinline__ void unpack2(ull v, float& lo, float& hi) {
    asm("mov.b64 {%0,%1}, %2;" : "=f"(lo), "=f"(hi) : "l"(v));
}
__device__ __forceinline__ ull fma2(ull a, ull b, ull c) {
    ull d; asm("fma.rn.f32x2 %0, %1, %2, %3;" : "=l"(d) : "l"(a), "l"(b), "l"(c)); return d;
}
__device__ __forceinline__ ull mul2(ull a, ull b) {
    ull d; asm("mul.rn.f32x2 %0, %1, %2;" : "=l"(d) : "l"(a), "l"(b)); return d;
}
__device__ __forceinline__ float shxor(float v, int m) {
    return __shfl_xor_sync(0xffffffffu, v, m, 32);
}

// angle-step literals (phi = pi/30)
#define PHI 0.10471975511965977f
#define CA1 0.9945218953682733f   // cos(phi)
#define SA1 0.1045284632676535f   // sin(phi)
#define C8  0.6691306063588582f   // cos(8*phi)
#define S8  0.7431448254773942f   // sin(8*phi)

__global__ void __launch_bounds__(NTHREADS)
robust_attn_kernel(const float* __restrict__ q, const float* __restrict__ k,
                   const float* __restrict__ v, float* __restrict__ out, int G)
{
    __shared__ float sK[BLK_PER_CTA * SST];
    __shared__ float sV[BLK_PER_CTA * SST];

    const int tid = threadIdx.x;
    const int blk0 = blockIdx.x * BLK_PER_CTA;
    const int nvalid = min(BLK_PER_CTA, G - blk0);
    const int nflt = nvalid * (W * DIM);
    const size_t base0 = (size_t)blk0 * (W * DIM);

    // ---- cooperative fill: relu'd K,V for 4 blocks (960 float4 each array) ----
    const float4* gk = (const float4*)(k + base0);
    const float4* gv = (const float4*)(v + base0);
    #pragma unroll
    for (int it = 0; it < 8; ++it) {
        int i4 = it * NTHREADS + tid;             // 0..1023
        if (i4 < 960 && i4 * 4 < nflt) {
            int lb  = i4 / 240;
            int pos = (i4 - lb * 240) * 4;
            float4 a = gk[i4];
            a.x = fmaxf(a.x, 0.f); a.y = fmaxf(a.y, 0.f);
            a.z = fmaxf(a.z, 0.f); a.w = fmaxf(a.w, 0.f);
            *(float4*)&sK[lb * SST + pos] = a;
            float4 b = gv[i4];
            b.x = fmaxf(b.x, 0.f); b.y = fmaxf(b.y, 0.f);
            b.z = fmaxf(b.z, 0.f); b.w = fmaxf(b.w, 0.f);
            *(float4*)&sV[lb * SST + pos] = b;
        }
    }
    __syncthreads();

    const int warp = tid >> 5;
    const int blk = blk0 + warp;
    if (blk >= G) return;

    const int lane = tid & 31;
    const int g = lane & 7;        // row group: rows g and g+8
    const int d = lane >> 3;       // dim group: dims [16d, 16d+16)
    const int doff = d * 16;
    const size_t base = (size_t)blk * (W * DIM);

    // ---- per-lane cos/sin of own row angles ----
    float ci[2], si[2];
    {
        float a = (float)g * PHI;
        __sincosf(a, &si[0], &ci[0]);
        // refine with exact values cheaply: use accurate sinf/cosf instead
        si[0] = sinf(a); ci[0] = cosf(a);
        ci[1] = ci[0] * C8 - si[0] * S8;
        si[1] = si[0] * C8 + ci[0] * S8;
    }

    // ---- load + relu q for my 2 rows x 16 dims ----
    ull q2[2][8];
    #pragma unroll
    for (int t = 0; t < 2; ++t) {
        int row = g + 8 * t; if (row > W - 1) row = W - 1;
        const float4* qp = (const float4*)(q + base + row * DIM + doff);
        #pragma unroll
        for (int c = 0; c < 4; ++c) {
            float4 f = qp[c];
            q2[t][2 * c]     = pack2(fmaxf(f.x, 0.f), fmaxf(f.y, 0.f));
            q2[t][2 * c + 1] = pack2(fmaxf(f.z, 0.f), fmaxf(f.w, 0.f));
        }
    }

    ull acc[2][8];
    #pragma unroll
    for (int t = 0; t < 2; ++t)
        #pragma unroll
        for (int e = 0; e < 8; ++e) acc[t][e] = 0ULL;
    float dn[2] = {0.f, 0.f};

    // ---- fused pass over j: packed K,V straight from smem ----
    float cj = 1.0f, sj = 0.0f;    // cos/sin(j*phi)
    #pragma unroll
    for (int j = 0; j < W; ++j) {
        const ulonglong2* kp = (const ulonglong2*)&sK[warp * SST + j * DIM + doff];
        ulonglong2 k0 = kp[0], k1 = kp[1], k2 = kp[2], k3 = kp[3];
        const ulonglong2* vp = (const ulonglong2*)&sV[warp * SST + j * DIM + doff];
        ulonglong2 v0 = vp[0], v1 = vp[1], v2 = vp[2], v3 = vp[3];
        ull kk[8] = {k0.x, k0.y, k1.x, k1.y, k2.x, k2.y, k3.x, k3.y};
        ull vv[8] = {v0.x, v0.y, v1.x, v1.y, v2.x, v2.y, v3.x, v3.y};

        #pragma unroll
        for (int t = 0; t < 2; ++t) {
            if (t == 1 || j <= 7) {          // compile-time skip of impossible pairs
                ull a0 = mul2(q2[t][0], kk[0]);
                ull a1 = mul2(q2[t][1], kk[1]);
                a0 = fma2(q2[t][2], kk[2], a0);
                a1 = fma2(q2[t][3], kk[3], a1);
                a0 = fma2(q2[t][4], kk[4], a0);
                a1 = fma2(q2[t][5], kk[5], a1);
                a0 = fma2(q2[t][6], kk[6], a0);
                a1 = fma2(q2[t][7], kk[7], a1);
                float x0, x1, y0, y1;
                unpack2(a0, x0, x1); unpack2(a1, y0, y1);
                float pf = (x0 + x1) + (y0 + y1);
                // 2-round segmented reduction over the 4 dim-groups
                pf += shxor(pf, 8);
                pf += shxor(pf, 16);
                float s = pf * (ci[t] * cj + si[t] * sj);
                // runtime causality where it depends on g
                if (t == 0) { if (j >= 1) s = (g >= j)     ? s : 0.f; }
                else        { if (j >= 9) s = (g >= j - 8) ? s : 0.f; }
                dn[t] += s;
                ull s2 = pack2(s, s);
                acc[t][0] = fma2(s2, vv[0], acc[t][0]);
                acc[t][1] = fma2(s2, vv[1], acc[t][1]);
                acc[t][2] = fma2(s2, vv[2], acc[t][2]);
                acc[t][3] = fma2(s2, vv[3], acc[t][3]);
                acc[t][4] = fma2(s2, vv[4], acc[t][4]);
                acc[t][5] = fma2(s2, vv[5], acc[t][5]);
                acc[t][6] = fma2(s2, vv[6], acc[t][6]);
                acc[t][7] = fma2(s2, vv[7], acc[t][7]);
            }
        }
        // advance cos/sin(j*phi)
        float cjn = cj * CA1 - sj * SA1;
        sj = sj * CA1 + cj * SA1;
        cj = cjn;
    }

    // ---- normalize + store ----
    #pragma unroll
    for (int t = 0; t < 2; ++t) {
        int row = g + 8 * t;
        if (row < W) {
            float rdt = __fdividef(1.0f, fmaxf(dn[t], EPS));
            ull r2 = pack2(rdt, rdt);
            ulonglong2* op = (ulonglong2*)(out + base + row * DIM + doff);
            ulonglong2 o;
            o.x = mul2(acc[t][0], r2); o.y = mul2(acc[t][1], r2); op[0] = o;
            o.x = mul2(acc[t][2], r2); o.y = mul2(acc[t][3], r2); op[1] = o;
            o.x = mul2(acc[t][4], r2); o.y = mul2(acc[t][5], r2); op[2] = o;
            o.x = mul2(acc[t][6], r2); o.y = mul2(acc[t][7], r2); op[3] = o;
        }
    }
}

extern "C" void kernel_launch(void* const* d_in, const int* in_sizes, int n_in,
                              void* d_out, int out_size) {
    const float* q = (const float*)d_in[0];
    const float* k = (const float*)d_in[1];
    const float* v = (const float*)d_in[2];
    float* out = (float*)d_out;

    int n = in_sizes[0];            // B*H*L*D
    int G = n / (W * DIM);          // number of attention blocks (20480)
    int grid = (G + BLK_PER_CTA - 1) / BLK_PER_CTA;
    robust_attn_kernel<<<grid, NTHREADS>>>(q, k, v, out, G);
}